// round 6
// baseline (speedup 1.0000x reference)
#include <cuda_runtime.h>

// ButterflyLinear, fused single kernel, occupancy-tuned.
// Math: stage 0 pairs (j, j^1); stages 1..11 all pair (j, j^2) => the whole
// 12-stage network is block-diagonal in 4-element groups. Each thread folds
// its group's 12 stage 2x2s into a 4x4 A_g in registers (24 L2-resident
// float4 loads + ~180 FMA, once per block), then streams T_PER=16 tokens.
// R5 lesson: T_PER=64 + regs=79 starved DRAM (58.6%). This round: T_PER=16
// (2048 blocks, the config that measured 70%+ DRAM) and launch_bounds
// (256,5) to cap regs at 48 so ptxas can't hoist all 24 fold loads.

#define TOKENS 8192
#define NCOLS  4096
#define DEPTH  12
#define GROUPS (NCOLS / 4)   // 1024
#define PAIRS  (NCOLS / 2)   // 2048 factor pairs per stage
#define T_PER  16            // tokens per thread -> 2048 blocks

// ---------------------------------------------------------------------------
// factors layout: F[stage][pair][c][d] as float4 per pair:
//   f.x=f[0][0], f.y=f[0][1], f.z=f[1][0], f.w=f[1][1]
// Stage semantics: y[d] = sum_c pair_in[c] * f[c][d]
// ---------------------------------------------------------------------------
__global__ void __launch_bounds__(256, 5)
butterfly_fused(const float4* __restrict__ F4,
                const float4* __restrict__ x,
                const float4* __restrict__ bias4,
                float4* __restrict__ out) {
    int g  = blockIdx.x * blockDim.x + threadIdx.x;  // 0..GROUPS-1
    int t0 = blockIdx.y * T_PER;
    int j0 = 4 * g;

    const float4* xp = x   + (size_t)t0 * GROUPS + g;
    float4*       op = out + (size_t)t0 * GROUPS + g;

    // First stream chunk in flight before/during the fold (hides fold latency).
    float4 v0 = __ldcs(xp + 0 * GROUPS);
    float4 v1 = __ldcs(xp + 1 * GROUPS);
    float4 v2 = __ldcs(xp + 2 * GROUPS);
    float4 v3 = __ldcs(xp + 3 * GROUPS);
    float4 b  = bias4[g];

    // ---- fold the 12 stages into a 4x4 (row-major: a{row}{col}) ----
    float a00, a01, a02, a03, a10, a11, a12, a13;
    float a20, a21, a22, a23, a30, a31, a32, a33;
    {
        float4 f0 = __ldg(F4 + 2 * g);
        float4 f1 = __ldg(F4 + 2 * g + 1);
        a00 = f0.x; a01 = f0.z; a02 = 0.f;  a03 = 0.f;
        a10 = f0.y; a11 = f0.w; a12 = 0.f;  a13 = 0.f;
        a20 = 0.f;  a21 = 0.f;  a22 = f1.x; a23 = f1.z;
        a30 = 0.f;  a31 = 0.f;  a32 = f1.y; a33 = f1.w;
    }
    #pragma unroll
    for (int s = 1; s < DEPTH; s++) {
        int block = 1 << (s + 1);
        int pA = ((j0 >> (s + 1)) << s) | ((j0 & (block - 1)) >> 2);
        int pB = pA + (1 << (s - 1));
        float4 fA = __ldg(F4 + s * PAIRS + pA);   // mixes rows (0,2)
        float4 fB = __ldg(F4 + s * PAIRS + pB);   // mixes rows (1,3)
        float r0, r2;
        r0 = a00; r2 = a20; a00 = fA.x*r0 + fA.z*r2; a20 = fA.y*r0 + fA.w*r2;
        r0 = a01; r2 = a21; a01 = fA.x*r0 + fA.z*r2; a21 = fA.y*r0 + fA.w*r2;
        r0 = a02; r2 = a22; a02 = fA.x*r0 + fA.z*r2; a22 = fA.y*r0 + fA.w*r2;
        r0 = a03; r2 = a23; a03 = fA.x*r0 + fA.z*r2; a23 = fA.y*r0 + fA.w*r2;
        float r1, r3;
        r1 = a10; r3 = a30; a10 = fB.x*r1 + fB.z*r3; a30 = fB.y*r1 + fB.w*r3;
        r1 = a11; r3 = a31; a11 = fB.x*r1 + fB.z*r3; a31 = fB.y*r1 + fB.w*r3;
        r1 = a12; r3 = a32; a12 = fB.x*r1 + fB.z*r3; a32 = fB.y*r1 + fB.w*r3;
        r1 = a13; r3 = a33; a13 = fB.x*r1 + fB.z*r3; a33 = fB.y*r1 + fB.w*r3;
    }

    // ---- stream T_PER tokens: software-pipelined chunks of 4 ----
    #pragma unroll
    for (int ii = 0; ii < T_PER; ii += 4) {
        float4 r0, r1, r2, r3;
        r0.x = b.x + v0.x*a00 + v0.y*a01 + v0.z*a02 + v0.w*a03;
        r0.y = b.y + v0.x*a10 + v0.y*a11 + v0.z*a12 + v0.w*a13;
        r0.z = b.z + v0.x*a20 + v0.y*a21 + v0.z*a22 + v0.w*a23;
        r0.w = b.w + v0.x*a30 + v0.y*a31 + v0.z*a32 + v0.w*a33;

        r1.x = b.x + v1.x*a00 + v1.y*a01 + v1.z*a02 + v1.w*a03;
        r1.y = b.y + v1.x*a10 + v1.y*a11 + v1.z*a12 + v1.w*a13;
        r1.z = b.z + v1.x*a20 + v1.y*a21 + v1.z*a22 + v1.w*a23;
        r1.w = b.w + v1.x*a30 + v1.y*a31 + v1.z*a32 + v1.w*a33;

        r2.x = b.x + v2.x*a00 + v2.y*a01 + v2.z*a02 + v2.w*a03;
        r2.y = b.y + v2.x*a10 + v2.y*a11 + v2.z*a12 + v2.w*a13;
        r2.z = b.z + v2.x*a20 + v2.y*a21 + v2.z*a22 + v2.w*a23;
        r2.w = b.w + v2.x*a30 + v2.y*a31 + v2.z*a32 + v2.w*a33;

        r3.x = b.x + v3.x*a00 + v3.y*a01 + v3.z*a02 + v3.w*a03;
        r3.y = b.y + v3.x*a10 + v3.y*a11 + v3.z*a12 + v3.w*a13;
        r3.z = b.z + v3.x*a20 + v3.y*a21 + v3.z*a22 + v3.w*a23;
        r3.w = b.w + v3.x*a30 + v3.y*a31 + v3.z*a32 + v3.w*a33;

        if (ii + 4 < T_PER) {
            v0 = __ldcs(xp + (size_t)(ii + 4) * GROUPS);
            v1 = __ldcs(xp + (size_t)(ii + 5) * GROUPS);
            v2 = __ldcs(xp + (size_t)(ii + 6) * GROUPS);
            v3 = __ldcs(xp + (size_t)(ii + 7) * GROUPS);
        }

        __stcs(op + (size_t)(ii + 0) * GROUPS, r0);
        __stcs(op + (size_t)(ii + 1) * GROUPS, r1);
        __stcs(op + (size_t)(ii + 2) * GROUPS, r2);
        __stcs(op + (size_t)(ii + 3) * GROUPS, r3);
    }
}

// ---------------------------------------------------------------------------
extern "C" void kernel_launch(void* const* d_in, const int* in_sizes, int n_in,
                              void* d_out, int out_size) {
    const float* x = nullptr;
    const float* factors = nullptr;
    const float* bias = nullptr;
    for (int i = 0; i < n_in; i++) {
        if (in_sizes[i] == TOKENS * NCOLS)            x = (const float*)d_in[i];
        else if (in_sizes[i] == DEPTH * PAIRS * 4)    factors = (const float*)d_in[i];
        else if (in_sizes[i] == NCOLS)                bias = (const float*)d_in[i];
    }

    dim3 grid(GROUPS / 256, TOKENS / T_PER);   // (4, 512) = 2048 blocks
    butterfly_fused<<<grid, 256>>>((const float4*)factors,
                                   (const float4*)x,
                                   (const float4*)bias,
                                   (float4*)d_out);
}

// round 7
// speedup vs baseline: 1.3849x; 1.3849x over previous
#include <cuda_runtime.h>

// ButterflyLinear: 12 butterfly stages on N=4096, TOKENS=8192.
// Stage 0 pairs (j, j^1); stages 1..11 all pair (j, j^2) => transform is
// block-diagonal in 4-element groups. Two kernels (fusion regressed twice:
// the per-thread fold is a serial L2-latency chain that steals registers
// from the streaming loop). Kernel 1 folds per-group 4x4s (column-parallel,
// 4096 threads). Kernel 2 streams out = blockdiag(A)*x + bias.

#define TOKENS 8192
#define NCOLS  4096
#define DEPTH  12
#define GROUPS (NCOLS / 4)   // 1024
#define PAIRS  (NCOLS / 2)   // 2048 factor pairs per stage
#define T_PER  8             // tokens per thread -> 4096 blocks (small tail)

// Scratch: 1024 groups x 4 columns (each column = float4) = 64 KB.
// g_C[g*4+e] = (A[0][e], A[1][e], A[2][e], A[3][e])
__device__ float4 g_C[GROUPS * 4];

// ---------------------------------------------------------------------------
// Kernel 1: one thread per (group, column); column-separable fold with
// front-batched MLP=24 loads (one DRAM round-trip).
// factors layout: F[stage][pair][c][d] as float4 per pair:
//   f.x=f[0][0], f.y=f[0][1], f.z=f[1][0], f.w=f[1][1]
// Stage semantics: y[d] = sum_c pair_in[c] * f[c][d]
// ---------------------------------------------------------------------------
__global__ void butterfly_precompute(const float4* __restrict__ F4) {
    int t = blockIdx.x * blockDim.x + threadIdx.x;   // 0..4095
    int g = t >> 2;
    int e = t & 3;
    int j0 = 4 * g;

    float4 fa[DEPTH], fb[DEPTH];
    fa[0] = F4[2 * g];
    fb[0] = F4[2 * g + 1];
    #pragma unroll
    for (int s = 1; s < DEPTH; s++) {
        int block = 1 << (s + 1);
        int pA = ((j0 >> (s + 1)) << s) | ((j0 & (block - 1)) >> 2);
        int pB = pA + (1 << (s - 1));
        fa[s] = F4[s * PAIRS + pA];
        fb[s] = F4[s * PAIRS + pB];
    }

    float A0, A1, A2, A3;
    {
        float4 f0 = fa[0], f1 = fb[0];
        bool lo = (e < 2);
        float4 f = lo ? f0 : f1;
        float u = (e & 1) ? f.z : f.x;
        float v = (e & 1) ? f.w : f.y;
        A0 = lo ? u : 0.f;
        A1 = lo ? v : 0.f;
        A2 = lo ? 0.f : u;
        A3 = lo ? 0.f : v;
    }

    #pragma unroll
    for (int s = 1; s < DEPTH; s++) {
        float a00 = fa[s].x, a01 = fa[s].y, a10 = fa[s].z, a11 = fa[s].w;
        float b00 = fb[s].x, b01 = fb[s].y, b10 = fb[s].z, b11 = fb[s].w;
        float r0 = A0, r1 = A1, r2 = A2, r3 = A3;
        A0 = a00 * r0 + a10 * r2;
        A2 = a01 * r0 + a11 * r2;
        A1 = b00 * r1 + b10 * r3;
        A3 = b01 * r1 + b11 * r3;
    }

    g_C[t] = make_float4(A0, A1, A2, A3);
}

// ---------------------------------------------------------------------------
// Kernel 2: out[t, group g] = A_g * x[t, g] + bias_g (column-major A):
//   r = b + v.x*c0 + v.y*c1 + v.z*c2 + v.w*c3
// Simple batch-of-4 load/compute/store (the form that measured 37.6us).
// ---------------------------------------------------------------------------
__global__ void __launch_bounds__(256)
butterfly_apply(const float4* __restrict__ x,
                const float4* __restrict__ bias4,
                float4* __restrict__ out) {
    int g  = blockIdx.x * blockDim.x + threadIdx.x;  // 0..GROUPS-1
    int t0 = blockIdx.y * T_PER;

    float4 c0 = g_C[g * 4 + 0];
    float4 c1 = g_C[g * 4 + 1];
    float4 c2 = g_C[g * 4 + 2];
    float4 c3 = g_C[g * 4 + 3];
    float4 b  = bias4[g];

    const float4* xp = x   + (size_t)t0 * GROUPS + g;
    float4*       op = out + (size_t)t0 * GROUPS + g;

    #pragma unroll
    for (int ii = 0; ii < T_PER; ii += 4) {
        float4 v0 = __ldcs(xp + (size_t)(ii + 0) * GROUPS);
        float4 v1 = __ldcs(xp + (size_t)(ii + 1) * GROUPS);
        float4 v2 = __ldcs(xp + (size_t)(ii + 2) * GROUPS);
        float4 v3 = __ldcs(xp + (size_t)(ii + 3) * GROUPS);

        float4 r0, r1, r2, r3;
        r0.x = b.x + v0.x*c0.x + v0.y*c1.x + v0.z*c2.x + v0.w*c3.x;
        r0.y = b.y + v0.x*c0.y + v0.y*c1.y + v0.z*c2.y + v0.w*c3.y;
        r0.z = b.z + v0.x*c0.z + v0.y*c1.z + v0.z*c2.z + v0.w*c3.z;
        r0.w = b.w + v0.x*c0.w + v0.y*c1.w + v0.z*c2.w + v0.w*c3.w;

        r1.x = b.x + v1.x*c0.x + v1.y*c1.x + v1.z*c2.x + v1.w*c3.x;
        r1.y = b.y + v1.x*c0.y + v1.y*c1.y + v1.z*c2.y + v1.w*c3.y;
        r1.z = b.z + v1.x*c0.z + v1.y*c1.z + v1.z*c2.z + v1.w*c3.z;
        r1.w = b.w + v1.x*c0.w + v1.y*c1.w + v1.z*c2.w + v1.w*c3.w;

        r2.x = b.x + v2.x*c0.x + v2.y*c1.x + v2.z*c2.x + v2.w*c3.x;
        r2.y = b.y + v2.x*c0.y + v2.y*c1.y + v2.z*c2.y + v2.w*c3.y;
        r2.z = b.z + v2.x*c0.z + v2.y*c1.z + v2.z*c2.z + v2.w*c3.z;
        r2.w = b.w + v2.x*c0.w + v2.y*c1.w + v2.z*c2.w + v2.w*c3.w;

        r3.x = b.x + v3.x*c0.x + v3.y*c1.x + v3.z*c2.x + v3.w*c3.x;
        r3.y = b.y + v3.x*c0.y + v3.y*c1.y + v3.z*c2.y + v3.w*c3.y;
        r3.z = b.z + v3.x*c0.z + v3.y*c1.z + v3.z*c2.z + v3.w*c3.z;
        r3.w = b.w + v3.x*c0.w + v3.y*c1.w + v3.z*c2.w + v3.w*c3.w;

        __stcs(op + (size_t)(ii + 0) * GROUPS, r0);
        __stcs(op + (size_t)(ii + 1) * GROUPS, r1);
        __stcs(op + (size_t)(ii + 2) * GROUPS, r2);
        __stcs(op + (size_t)(ii + 3) * GROUPS, r3);
    }
}

// ---------------------------------------------------------------------------
extern "C" void kernel_launch(void* const* d_in, const int* in_sizes, int n_in,
                              void* d_out, int out_size) {
    const float* x = nullptr;
    const float* factors = nullptr;
    const float* bias = nullptr;
    for (int i = 0; i < n_in; i++) {
        if (in_sizes[i] == TOKENS * NCOLS)            x = (const float*)d_in[i];
        else if (in_sizes[i] == DEPTH * PAIRS * 4)    factors = (const float*)d_in[i];
        else if (in_sizes[i] == NCOLS)                bias = (const float*)d_in[i];
    }

    // Kernel 1: 4096 threads = 1 per (group, column).
    butterfly_precompute<<<32, 128>>>((const float4*)factors);

    // Kernel 2: (4, 1024) = 4096 blocks, 8 tokens per thread.
    dim3 grid(GROUPS / 256, TOKENS / T_PER);
    butterfly_apply<<<grid, 256>>>((const float4*)x,
                                   (const float4*)bias,
                                   (float4*)d_out);
}